// round 7
// baseline (speedup 1.0000x reference)
#include <cuda_runtime.h>
#include <stdint.h>

// Attention: B=256,H=32,S=16,D=64. scale=1/sqrt(8). +ones mask (cancels in softmax).
// Dropout p=0.3, jax partitionable threefry (verified R5):
//   bits[i] = out0 ^ out1 of threefry2x32(key=(0,42), x0=0, x1=i)
//   uniform = bitcast((bits>>9)|0x3f800000)-1 ; keep = uniform < 0.7f.
//
// 2 heads / 128-thread block; 2 warps per head (8 rows each).
// lane = (r_loc = lane>>2, quarter = lane&3): 4 logits (cols 4j+q), 4 out float4 (4u+q).
// Smem swizzle: chunk c4 of row at slot row*16 + ((c4+row)&15)  -> all reads 1 wavefront.

#define HEADS_PER_BLOCK 2
#define NBLOCKS         4096        // 8192 heads / 2
#define PSTR            20          // ps stride: banks (20*rl + t) disjoint for rl 0..7, q 0..3

__device__ __forceinline__ uint32_t threefry2x32_xor_k042(uint32_t x0, uint32_t x1) {
    const uint32_t k0 = 0u;
    const uint32_t k1 = 42u;
    const uint32_t k2 = 0x1BD11BDAu ^ k0 ^ k1;
    x0 += k0; x1 += k1;
#define TF_R(R) { x0 += x1; x1 = __funnelshift_l(x1, x1, (R)); x1 ^= x0; }
    TF_R(13) TF_R(15) TF_R(26) TF_R(6)
    x0 += k1; x1 += k2 + 1u;
    TF_R(17) TF_R(29) TF_R(16) TF_R(24)
    x0 += k2; x1 += k0 + 2u;
    TF_R(13) TF_R(15) TF_R(26) TF_R(6)
    x0 += k0; x1 += k1 + 3u;
    TF_R(17) TF_R(29) TF_R(16) TF_R(24)
    x0 += k1; x1 += k2 + 4u;
    TF_R(13) TF_R(15) TF_R(26) TF_R(6)
    x0 += k2; x1 += k0 + 5u;
#undef TF_R
    return x0 ^ x1;
}

__device__ __forceinline__ float tf_uniform(uint32_t bits) {
    return __uint_as_float((bits >> 9) | 0x3f800000u) - 1.0f;
}

__global__ __launch_bounds__(128)
void attn_drop_kernel(const float* __restrict__ q,
                      const float* __restrict__ k,
                      const float* __restrict__ v,
                      float* __restrict__ out) {
    __shared__ float4 sq[HEADS_PER_BLOCK * 256];
    __shared__ float4 sk[HEADS_PER_BLOCK * 256];
    __shared__ float4 sv[HEADS_PER_BLOCK * 256];
    __shared__ float  ps[4][8 * PSTR];            // per-warp probability rows

    const int tid  = threadIdx.x;
    const int w    = tid >> 5;                    // warp 0..3
    const int lane = tid & 31;
    const int hl   = w >> 1;                      // head slot in block (0..1)
    const int rh   = w & 1;                       // row half (0: rows 0-7, 1: rows 8-15)
    const int hd   = blockIdx.x * HEADS_PER_BLOCK + hl;
    const int hb   = hl * 256;

    const int r_loc = lane >> 2;                  // 0..7
    const int qt    = lane & 3;                   // quarter 0..3
    const int r     = rh * 8 + r_loc;             // global row 0..15

    // ---- Stage both heads' q,k,v (block-cooperative, coalesced, swizzled) ----
    {
        const float4* qg = reinterpret_cast<const float4*>(q) + (size_t)blockIdx.x * 512;
        const float4* kg = reinterpret_cast<const float4*>(k) + (size_t)blockIdx.x * 512;
        const float4* vg = reinterpret_cast<const float4*>(v) + (size_t)blockIdx.x * 512;
        #pragma unroll
        for (int i = 0; i < 4; i++) {
            const int f    = i * 128 + tid;       // 0..511 over 2 heads
            const int ff   = f & 255;
            const int row  = ff >> 4;
            const int c4   = ff & 15;
            const int slot = (f & 256) + row * 16 + ((c4 + row) & 15);
            sq[slot] = qg[f];
            sk[slot] = kg[f];
            sv[slot] = vg[f];
        }
    }

    // ---- Dropout mask (hides LDG latency): 4 threefry calls per lane ----
    unsigned kmask = 0;
    const uint32_t fbase = (uint32_t)hd * 256u + (uint32_t)(r * 16 + qt);
    #pragma unroll
    for (int j = 0; j < 4; j++) {
        const uint32_t bits = threefry2x32_xor_k042(0u, fbase + 4u * (uint32_t)j);
        kmask |= (tf_uniform(bits) < 0.7f) ? (1u << j) : 0u;
    }

    __syncthreads();

    // ---- QK^T: lane computes logits[r][4j+qt], j=0..3 ----
    const float SCALE = 0.35355339059327373f;     // 1/sqrt(8)
    float acc[4] = {0.f, 0.f, 0.f, 0.f};

    #pragma unroll
    for (int dd = 0; dd < 16; dd++) {
        const float4 qc = sq[hb + r * 16 + ((dd + r) & 15)];
        #pragma unroll
        for (int j = 0; j < 4; j++) {
            const int c = 4 * j + qt;
            const float4 kc = sk[hb + c * 16 + ((dd + c) & 15)];
            acc[j] = fmaf(qc.x, kc.x,
                     fmaf(qc.y, kc.y,
                     fmaf(qc.z, kc.z,
                     fmaf(qc.w, kc.w, acc[j]))));
        }
    }

    // ---- softmax over the row (4 lanes share a row) ----
    float m = -1e30f;
    #pragma unroll
    for (int j = 0; j < 4; j++) {
        acc[j] = acc[j] * SCALE + 1.0f;           // additive ones mask
        m = fmaxf(m, acc[j]);
    }
    m = fmaxf(m, __shfl_xor_sync(0xffffffffu, m, 1));
    m = fmaxf(m, __shfl_xor_sync(0xffffffffu, m, 2));

    float s = 0.0f;
    #pragma unroll
    for (int j = 0; j < 4; j++) {
        acc[j] = __expf(acc[j] - m);
        s += acc[j];
    }
    s += __shfl_xor_sync(0xffffffffu, s, 1);
    s += __shfl_xor_sync(0xffffffffu, s, 2);
    const float inv = 1.0f / (s * 0.7f);          // normalize + dropout scale

    #pragma unroll
    for (int j = 0; j < 4; j++)
        ps[w][r_loc * PSTR + 4 * j + qt] = (kmask & (1u << j)) ? acc[j] * inv : 0.0f;

    __syncwarp();

    // ---- P @ V: lane accumulates out[r][(4u+qt)*4 .. +3], u=0..3 ----
    float4 o[4];
    #pragma unroll
    for (int u = 0; u < 4; u++) o[u] = make_float4(0.f, 0.f, 0.f, 0.f);

    #pragma unroll
    for (int t = 0; t < 16; t++) {
        const float pv = ps[w][r_loc * PSTR + t];
        #pragma unroll
        for (int u = 0; u < 4; u++) {
            const int cc = 4 * u + qt;
            const float4 vc = sv[hb + t * 16 + ((cc + t) & 15)];
            o[u].x = fmaf(pv, vc.x, o[u].x);
            o[u].y = fmaf(pv, vc.y, o[u].y);
            o[u].z = fmaf(pv, vc.z, o[u].z);
            o[u].w = fmaf(pv, vc.w, o[u].w);
        }
    }

    // ---- store (quartets cover contiguous 64B segments) ----
    float4* og = reinterpret_cast<float4*>(out) + (size_t)hd * 256 + r * 16;
    #pragma unroll
    for (int u = 0; u < 4; u++)
        og[4 * u + qt] = o[u];
}

extern "C" void kernel_launch(void* const* d_in, const int* in_sizes, int n_in,
                              void* d_out, int out_size) {
    const float* q = (const float*)d_in[0];
    const float* k = (const float*)d_in[1];
    const float* v = (const float*)d_in[2];
    float* out = (float*)d_out;
    (void)in_sizes; (void)n_in; (void)out_size;
    attn_drop_kernel<<<NBLOCKS, 128>>>(q, k, v, out);
}